// round 16
// baseline (speedup 1.0000x reference)
#include <cuda_runtime.h>
#include <math.h>

#define BATCH 512
#define TT 5
#define NPROB (BATCH*TT)

// ---------------- scratch (device globals: no allocation allowed) ----------------
__device__ float g_h1[BATCH*10*20*20];   // conv1+pool output
__device__ float g_h2[BATCH*320];        // conv2+pool output (flattened)
__device__ float g_pr[BATCH*20];
__device__ float g_v[BATCH*40];
__device__ __align__(16) float g_wT[118000];  // transposed weights

// ---------------- conv1: (B,1,50,50) -> conv 11x11 -> pool2 -> relu -> (B,10,20,20) ----
__global__ void conv1_kernel(const float* __restrict__ img,
                             const float* __restrict__ w,
                             const float* __restrict__ bias)
{
    __shared__ float sIm[2500];
    __shared__ float sW[1210];
    __shared__ float sB[10];
    int b = blockIdx.x;
    int tid = threadIdx.x;  // 0..399
    for (int i = tid; i < 2500; i += 400) sIm[i] = img[b*2500 + i];
    for (int i = tid; i < 1210; i += 400) sW[i] = w[i];
    if (tid < 10) sB[tid] = bias[tid];
    __syncthreads();

    int oy = tid / 20, ox = tid % 20;
    float acc[10][4];
#pragma unroll
    for (int c = 0; c < 10; c++) { acc[c][0]=0.f; acc[c][1]=0.f; acc[c][2]=0.f; acc[c][3]=0.f; }
    int iy0 = 2*oy, ix0 = 2*ox;
    for (int ky = 0; ky < 11; ky++) {
        const float* row0 = &sIm[(iy0+ky)*50 + ix0];
        const float* row1 = row0 + 50;
#pragma unroll
        for (int kx = 0; kx < 11; kx++) {
            float p00 = row0[kx], p01 = row0[kx+1];
            float p10 = row1[kx], p11 = row1[kx+1];
#pragma unroll
            for (int c = 0; c < 10; c++) {
                float wv = sW[c*121 + ky*11 + kx];
                acc[c][0] += wv*p00; acc[c][1] += wv*p01;
                acc[c][2] += wv*p10; acc[c][3] += wv*p11;
            }
        }
    }
#pragma unroll
    for (int c = 0; c < 10; c++) {
        float m = fmaxf(fmaxf(acc[c][0],acc[c][1]), fmaxf(acc[c][2],acc[c][3]));
        m += sB[c];
        g_h1[((b*10 + c)*20 + oy)*20 + ox] = fmaxf(m, 0.0f);
    }
}

// ---------------- conv2: (B,10,20,20) -> conv 5x5 (20 out) -> pool4 -> relu -> (B,320) ----
__global__ void conv2_kernel(const float* __restrict__ w,   // (20,10,5,5)
                             const float* __restrict__ bias)
{
    __shared__ __align__(16) float sm[9024];
    float* sIn = sm;          // 4000
    float* sW  = sm + 4000;   // 5000 rearranged: [ci][ky][kx][c]
    int b = blockIdx.x;
    int tid = threadIdx.x;    // 0..319
    for (int i = tid; i < 4000; i += 320) sIn[i] = g_h1[b*4000 + i];
    for (int i = tid; i < 5000; i += 320) {
        int c = i % 20;
        int r = i / 20;
        sW[i] = w[c*250 + r];
    }
    __syncthreads();

    bool active = tid < 256;
    int ix = tid & 3, iy = (tid>>2)&3, px = (tid>>4)&3, py = (tid>>6)&3;
    int Y = py*4 + iy, X = px*4 + ix;
    float acc[20];
#pragma unroll
    for (int c = 0; c < 20; c++) acc[c] = 0.0f;
    if (active) {
        for (int ci = 0; ci < 10; ci++) {
            const float* inp = &sIn[ci*400 + Y*20 + X];
#pragma unroll
            for (int ky = 0; ky < 5; ky++) {
#pragma unroll
                for (int kx = 0; kx < 5; kx++) {
                    float pix = inp[ky*20 + kx];
                    const float4* wp = (const float4*)&sW[(ci*25 + ky*5 + kx)*20];
#pragma unroll
                    for (int j = 0; j < 5; j++) {
                        float4 wv = wp[j];
                        acc[4*j+0] += wv.x*pix;
                        acc[4*j+1] += wv.y*pix;
                        acc[4*j+2] += wv.z*pix;
                        acc[4*j+3] += wv.w*pix;
                    }
                }
            }
        }
    }
    __syncthreads();
    float* sConv = sm;
    if (active) {
        int q = py*4 + px;
        int pos = iy*4 + ix;
#pragma unroll
        for (int c = 0; c < 20; c++) sConv[(c*16 + q)*16 + pos] = acc[c];
    }
    __syncthreads();
    {
        int c = tid / 16, qq = tid % 16;
        const float* p = &sConv[(c*16+qq)*16];
        float m = p[0];
#pragma unroll
        for (int k = 1; k < 16; k++) m = fmaxf(m, p[k]);
        m += bias[c];
        g_h2[b*320 + c*16 + qq] = fmaxf(m, 0.0f);
    }
}

// ---------------- weight transpose ----------------
__global__ void transpose_w(const float* __restrict__ w3, const float* __restrict__ w4,
                            const float* __restrict__ pw1, const float* __restrict__ vw1,
                            const float* __restrict__ pw2, const float* __restrict__ vw2,
                            const float* __restrict__ pw3, const float* __restrict__ vw3)
{
    int i = blockIdx.x*blockDim.x + threadIdx.x;
    if (i >= 118000) return;
    float v;
    if (i < 48000)       { int n=i%150, k=i/150;                 v = w3[n*320+k]; }
    else if (i < 63000)  { int j=i-48000;  int n=j%100, k=j/100; v = w4[n*150+k]; }
    else if (i < 77500)  { int j=i-63000;  int n=j%100, k=j/100; v = pw1[n*145+k]; }
    else if (i < 92000)  { int j=i-77500;  int n=j%100, k=j/100; v = vw1[n*145+k]; }
    else if (i < 102000) { int j=i-92000;  int n=j%100, k=j/100; v = pw2[n*100+k]; }
    else if (i < 112000) { int j=i-102000; int n=j%100, k=j/100; v = vw2[n*100+k]; }
    else if (i < 114000) { int j=i-112000; int n=j%20,  k=j/20;  v = pw3[n*100+k]; }
    else                 { int j=i-114000; int n=j%40,  k=j/40;  v = vw3[n*100+k]; }
    g_wT[i] = v;
}

// ---------------- fused MLP: 2 samples/block, deep-unroll (32 loads in flight) -------
__global__ __launch_bounds__(256) void mlp_kernel(const float* __restrict__ xtraj,
    const float* __restrict__ b3, const float* __restrict__ b4,
    const float* __restrict__ pb1, const float* __restrict__ vb1,
    const float* __restrict__ pb2, const float* __restrict__ vb2,
    const float* __restrict__ pb3, const float* __restrict__ vb3)
{
    __shared__ float sA[2][324];
    __shared__ float sB[2][204];
    int b0 = blockIdx.x*2;
    int tid = threadIdx.x;

    for (int i = tid; i < 640; i += 256) {
        int s = i / 320, k = i % 320;
        sA[s][k] = g_h2[(b0+s)*320 + k];
    }
    __syncthreads();

    // L1: 320 -> 150 relu
    if (tid < 150) {
        const float* W = g_wT + tid;
        float a0=0.f, a1=0.f, c0=0.f, c1=0.f;
#pragma unroll 16
        for (int k = 0; k < 320; k += 2) {
            float w0 = W[k*150], w1 = W[(k+1)*150];
            a0 = fmaf(sA[0][k],   w0, a0);
            a1 = fmaf(sA[1][k],   w0, a1);
            c0 = fmaf(sA[0][k+1], w1, c0);
            c1 = fmaf(sA[1][k+1], w1, c1);
        }
        float bb = b3[tid];
        sB[0][tid] = fmaxf(a0+c0+bb, 0.f);
        sB[1][tid] = fmaxf(a1+c1+bb, 0.f);
    }
    __syncthreads();

    // L2: 150 -> 100 relu
    float l2a = 0.f, l2b = 0.f;
    if (tid < 100) {
        const float* W = g_wT + 48000 + tid;
        float bb = b4[tid];
        float a0=0.f, a1=0.f, c0=0.f, c1=0.f;
#pragma unroll 16
        for (int k = 0; k < 150; k += 2) {
            float w0 = W[k*100], w1 = W[(k+1)*100];
            a0 = fmaf(sB[0][k],   w0, a0);
            a1 = fmaf(sB[1][k],   w0, a1);
            c0 = fmaf(sB[0][k+1], w1, c0);
            c1 = fmaf(sB[1][k+1], w1, c1);
        }
        l2a = fmaxf(a0+c0+bb, 0.f);
        l2b = fmaxf(a1+c1+bb, 0.f);
    }
    __syncthreads();
    if (tid < 100) { sA[0][tid] = l2a; sA[1][tid] = l2b; }
    for (int i = tid; i < 90; i += 256) {
        int s = i / 45, j = i % 45;
        sA[s][100+j] = xtraj[(b0+s)*45 + j];
    }
    __syncthreads();

    // L3 dual: 145 -> 100 (p) / 100 (v), relu
    if (tid < 200) {
        int half = tid >= 100;
        int n = half ? tid - 100 : tid;
        const float* W = g_wT + (half ? 77500 : 63000) + n;
        float bb = (half ? vb1 : pb1)[n];
        float a0=0.f, a1=0.f, c0=0.f, c1=0.f;
#pragma unroll 16
        for (int k = 0; k < 144; k += 2) {
            float w0 = W[k*100], w1 = W[(k+1)*100];
            a0 = fmaf(sA[0][k],   w0, a0);
            a1 = fmaf(sA[1][k],   w0, a1);
            c0 = fmaf(sA[0][k+1], w1, c0);
            c1 = fmaf(sA[1][k+1], w1, c1);
        }
        {
            float w0 = W[144*100];
            a0 = fmaf(sA[0][144], w0, a0);
            a1 = fmaf(sA[1][144], w0, a1);
        }
        sB[0][tid] = fmaxf(a0+c0+bb, 0.f);
        sB[1][tid] = fmaxf(a1+c1+bb, 0.f);
    }
    __syncthreads();

    // L4 dual: 100 -> 100 each head, relu
    float l4a = 0.f, l4b = 0.f;
    if (tid < 200) {
        int half = tid >= 100;
        int n = half ? tid - 100 : tid;
        int xoff = half ? 100 : 0;
        const float* W = g_wT + (half ? 102000 : 92000) + n;
        float bb = (half ? vb2 : pb2)[n];
        float a0=0.f, a1=0.f, c0=0.f, c1=0.f;
#pragma unroll 16
        for (int k = 0; k < 100; k += 2) {
            float w0 = W[k*100], w1 = W[(k+1)*100];
            a0 = fmaf(sB[0][xoff+k],   w0, a0);
            a1 = fmaf(sB[1][xoff+k],   w0, a1);
            c0 = fmaf(sB[0][xoff+k+1], w1, c0);
            c1 = fmaf(sB[1][xoff+k+1], w1, c1);
        }
        l4a = fmaxf(a0+c0+bb, 0.f);
        l4b = fmaxf(a1+c1+bb, 0.f);
    }
    __syncthreads();
    if (tid < 200) { sA[0][tid] = l4a; sA[1][tid] = l4b; }
    __syncthreads();

    // L5 dual: 100 -> 20 (p_r), 100 -> 40 (v), linear, to global
    if (tid < 20) {
        const float* W = g_wT + 112000 + tid;
        float bb = pb3[tid];
        float a0=0.f, a1=0.f, c0=0.f, c1=0.f;
#pragma unroll 16
        for (int k = 0; k < 100; k += 2) {
            float w0 = W[k*20], w1 = W[(k+1)*20];
            a0 = fmaf(sA[0][k],   w0, a0);
            a1 = fmaf(sA[1][k],   w0, a1);
            c0 = fmaf(sA[0][k+1], w1, c0);
            c1 = fmaf(sA[1][k+1], w1, c1);
        }
        g_pr[(b0+0)*20 + tid] = a0+c0+bb;
        g_pr[(b0+1)*20 + tid] = a1+c1+bb;
    } else if (tid >= 32 && tid < 72) {
        int n = tid - 32;
        const float* W = g_wT + 114000 + n;
        float bb = vb3[n];
        float a0=0.f, a1=0.f, c0=0.f, c1=0.f;
#pragma unroll 16
        for (int k = 0; k < 100; k += 2) {
            float w0 = W[k*40], w1 = W[(k+1)*40];
            a0 = fmaf(sA[0][100+k],   w0, a0);
            a1 = fmaf(sA[1][100+k],   w0, a1);
            c0 = fmaf(sA[0][100+k+1], w1, c0);
            c1 = fmaf(sA[1][100+k+1], w1, c1);
        }
        g_v[(b0+0)*40 + n] = a0+c0+bb;
        g_v[(b0+1)*40 + n] = a1+c1+bb;
    }
}

// ---------------- PDHG solver (scalar, proven; issue-bound at ~73%) + fused tail ------
struct Co {
    float a24,a25,a26,a27,a28,a29,a2a,a2b;
    float v0,v1,v2,v3,v4,v5;
    float fc0,fc1,fc2,fc3,fc4,fc5;
    float fe0,fe1,fe2,fe3,fe4,fe5,fe6,fe7;
};

__device__ __forceinline__ void amul(const Co& c, const float* s, float* az)
{
    az[0]  = s[4]+s[5]+s[6]+s[7]+s[8]+s[9];
    az[1]  = s[10]+s[11];
    {
        float p = c.a26*s[6] + c.a24*s[4] + c.a27*s[7] + c.a25*s[5];
        float q = c.a2a*s[10] + c.a28*s[8] + c.a2b*s[11] + c.a29*s[9];
        az[2] = p + q;
    }
    az[3]  = s[0] - c.v0*s[12] - c.v2*s[14];
    az[4]  = s[2] - c.v1*s[12] - c.v3*s[14];
    az[5]  = s[12] + s[14];
    az[6]  = s[1] - c.v2*s[13] - c.v4*s[15];
    az[7]  = s[3] - c.v3*s[13] - c.v5*s[15];
    az[8]  = s[13] + s[15];
    az[9]  = c.fc0*s[16] + c.fc2*s[18] - s[4];
    az[10] = c.fc1*s[16] + c.fc3*s[18] - s[6];
    az[11] = c.fc2*s[17] + c.fc4*s[19] - s[5];
    az[12] = c.fc3*s[17] + c.fc5*s[19] - s[7];
    az[13] = c.fe0*s[20] + c.fe2*s[21] - s[8];
    az[14] = c.fe1*s[20] + c.fe3*s[21] - s[10];
    az[15] = c.fe4*s[22] + c.fe6*s[23] - s[9];
    az[16] = c.fe5*s[22] + c.fe7*s[23] - s[11];
}

__device__ __forceinline__ void atmul(const Co& c, const float* y, float* g)
{
    g[0]  = y[3];  g[1] = y[6];  g[2] = y[4];  g[3] = y[7];
    g[4]  = y[0] + c.a24*y[2] - y[9];
    g[5]  = y[0] + c.a25*y[2] - y[11];
    g[6]  = y[0] + c.a26*y[2] - y[10];
    g[7]  = y[0] + c.a27*y[2] - y[12];
    g[8]  = y[0] + c.a28*y[2] - y[13];
    g[9]  = y[0] + c.a29*y[2] - y[15];
    g[10] = y[1] + c.a2a*y[2] - y[14];
    g[11] = y[1] + c.a2b*y[2] - y[16];
    g[12] = -c.v0*y[3] - c.v1*y[4] + y[5];
    g[13] = -c.v2*y[6] - c.v3*y[7] + y[8];
    g[14] = -c.v2*y[3] - c.v3*y[4] + y[5];
    g[15] = -c.v4*y[6] - c.v5*y[7] + y[8];
    g[16] = c.fc0*y[9]  + c.fc1*y[10];
    g[17] = c.fc2*y[11] + c.fc3*y[12];
    g[18] = c.fc2*y[9]  + c.fc3*y[10];
    g[19] = c.fc4*y[11] + c.fc5*y[12];
    g[20] = c.fe0*y[13] + c.fe1*y[14];
    g[21] = c.fe2*y[13] + c.fe3*y[14];
    g[22] = c.fe4*y[15] + c.fe5*y[16];
    g[23] = c.fe6*y[15] + c.fe7*y[16];
}

__global__ __launch_bounds__(32) void pdhg_kernel(const float* __restrict__ xtraj,
                                                  const float* __restrict__ x,
                                                  float* __restrict__ out)
{
    int p = blockIdx.x*blockDim.x + threadIdx.x;
    if (p >= NPROB) return;
    int b = p / TT, t = p % TT;
    const float* xt = xtraj + b*45;
    const float* xx = x + b*160;

    float r0 = xt[t], r1 = xt[5+t];
    float ddr0 = xt[30+t], ddr1 = xt[35+t], ddr2 = xt[40+t];

    Co c;
    c.fc0 = xx[20+t]; c.fc1 = xx[25+t]; c.fc2 = xx[30+t];
    c.fc3 = xx[35+t]; c.fc4 = xx[40+t]; c.fc5 = xx[45+t];
    float pe0 = xx[60+t], pe1 = xx[65+t], pe2 = xx[70+t], pe3 = xx[75+t];
    c.fe0 = xx[80+t];  c.fe1 = xx[85+t];  c.fe2 = xx[90+t];  c.fe3 = xx[95+t];
    c.fe4 = xx[100+t]; c.fe5 = xx[105+t]; c.fe6 = xx[110+t]; c.fe7 = xx[115+t];
    const float* vv = g_v + b*40;
    c.v0 = vv[t];    c.v1 = vv[5+t];  c.v2 = vv[10+t];
    c.v3 = vv[15+t]; c.v4 = vv[20+t]; c.v5 = vv[25+t];
    const float* pp = g_pr + b*20;
    float pr0 = pp[t], pr1 = pp[5+t], pr2 = pp[10+t], pr3 = pp[15+t];
    c.a24 = -(pr2 - r1); c.a25 = -(pr3 - r1); c.a26 = pr0 - r0; c.a27 = pr1 - r0;
    c.a28 = -(pe2 - r1); c.a29 = -(pe3 - r1); c.a2a = pe0 - r0; c.a2b = pe1 - r0;

    // ----- spectral norm: 25 power iterations -----
    float u[24];
#pragma unroll
    for (int i = 0; i < 24; i++) u[i] = 1.0f;
    for (int it = 0; it < 25; it++) {
        float w[17], un[24];
        amul(c, u, w);
        atmul(c, w, un);
        float s = 0.0f;
#pragma unroll
        for (int i = 0; i < 24; i++) s += un[i]*un[i];
        float inv = 1.0f/(sqrtf(s) + 1e-12f);
#pragma unroll
        for (int i = 0; i < 24; i++) u[i] = un[i]*inv;
    }
    float w17[17];
    amul(c, u, w17);
    float s = 0.0f;
#pragma unroll
    for (int e = 0; e < 17; e++) s += w17[e]*w17[e];
    float L = sqrtf(s);
    float tau = 0.9f/(L + 1e-8f);
    float sig = tau;

    // ----- PDHG, 400 iterations -----
    float z[24], zb[24], y[17];
#pragma unroll
    for (int i = 0; i < 24; i++) { z[i] = 0.0f; zb[i] = 0.0f; }
#pragma unroll
    for (int e = 0; e < 17; e++) y[e] = 0.0f;

    for (int it = 0; it < 400; it++) {
        float az[17];
        amul(c, zb, az);
        y[0] += sig*(az[0] - ddr0);
        y[1] += sig*(az[1] - ddr1);
        y[2] += sig*(az[2] - ddr2);
        y[3] += sig*az[3];
        y[4] += sig*az[4];
        y[5] += sig*(az[5] - 1.0f);
        y[6] += sig*az[6];
        y[7] += sig*az[7];
        y[8] += sig*(az[8] - 1.0f);
#pragma unroll
        for (int e = 9; e < 17; e++) y[e] += sig*az[e];

        float g[24];
        atmul(c, y, g);
#pragma unroll
        for (int i = 0; i < 24; i++) g[i] = z[i] - tau*g[i];

        float zn[24];
#pragma unroll
        for (int i = 0; i < 4; i++) zn[i] = g[i];
#pragma unroll
        for (int i = 4; i < 8; i++) {
            float a = fabsf(g[i]) - tau;
            zn[i] = (a > 0.0f) ? copysignf(a, g[i]) : 0.0f;
        }
#pragma unroll
        for (int i = 8; i < 12; i++) zn[i] = g[i];
#pragma unroll
        for (int i = 12; i < 24; i++) zn[i] = fmaxf(g[i], 0.0f);
#pragma unroll
        for (int i = 0; i < 24; i++) {
            zb[i] = 2.0f*zn[i] - z[i];
            z[i] = zn[i];
        }
    }

    // ----- write p, f parts (scaled by 100) -----
#pragma unroll
    for (int i = 0; i < 4; i++) out[b*100 + i*5 + t]      = 100.0f * z[i];
#pragma unroll
    for (int i = 0; i < 4; i++) out[b*100 + 20 + i*5 + t] = 100.0f * z[4+i];

    // ----- fused tail: this thread writes 12 of the 60 tail outputs of sample b -----
#pragma unroll
    for (int j = 0; j < 12; j++) {
        int jj = t*12 + j;
        if (jj < 20) out[b*100 + 40 + jj] = 1000.0f*(g_pr[b*20 + jj] - xx[jj]);
        else {
            int k = jj - 20;
            out[b*100 + 60 + k] = 1000.0f*(g_v[b*40 + k] - xx[120 + k]);
        }
    }
}

// ---------------- launch ----------------
extern "C" void kernel_launch(void* const* d_in, const int* in_sizes, int n_in,
                              void* d_out, int out_size)
{
    const float* xtraj = (const float*)d_in[0];
    const float* x     = (const float*)d_in[1];
    const float* x_img = (const float*)d_in[2];
    const float* cw1   = (const float*)d_in[3];
    const float* cb1   = (const float*)d_in[4];
    const float* cw2   = (const float*)d_in[5];
    const float* cb2   = (const float*)d_in[6];
    const float* w3    = (const float*)d_in[7];
    const float* b3    = (const float*)d_in[8];
    const float* w4    = (const float*)d_in[9];
    const float* b4    = (const float*)d_in[10];
    const float* pw1   = (const float*)d_in[11];
    const float* pb1   = (const float*)d_in[12];
    const float* pw2   = (const float*)d_in[13];
    const float* pb2   = (const float*)d_in[14];
    const float* pw3   = (const float*)d_in[15];
    const float* pb3   = (const float*)d_in[16];
    const float* vw1   = (const float*)d_in[17];
    const float* vb1   = (const float*)d_in[18];
    const float* vw2   = (const float*)d_in[19];
    const float* vb2   = (const float*)d_in[20];
    const float* vw3   = (const float*)d_in[21];
    const float* vb3   = (const float*)d_in[22];
    float* out = (float*)d_out;

    transpose_w<<<(118000 + 255)/256, 256>>>(w3, w4, pw1, vw1, pw2, vw2, pw3, vw3);
    conv1_kernel<<<BATCH, 400>>>(x_img, cw1, cb1);
    conv2_kernel<<<BATCH, 320>>>(cw2, cb2);
    mlp_kernel<<<BATCH/2, 256>>>(xtraj, b3, b4, pb1, vb1, pb2, vb2, pb3, vb3);
    pdhg_kernel<<<(NPROB + 31)/32, 32>>>(xtraj, x, out);
}

// round 17
// speedup vs baseline: 1.0323x; 1.0323x over previous
#include <cuda_runtime.h>
#include <math.h>

#define BATCH 512
#define TT 5
#define NPROB (BATCH*TT)

// ---------------- scratch (device globals: no allocation allowed) ----------------
__device__ float g_h1[BATCH*10*20*20];   // conv1+pool output
__device__ float g_h2[BATCH*320];        // conv2+pool output (flattened)
__device__ float g_pr[BATCH*20];
__device__ float g_v[BATCH*40];
__device__ __align__(16) float g_wT[118000];  // transposed weights

// ================= packed f32x2 helpers =================
typedef unsigned long long u64;
__device__ __forceinline__ u64 mkf2(float lo, float hi){ u64 r; asm("mov.b64 %0,{%1,%2};":"=l"(r):"f"(lo),"f"(hi)); return r; }
__device__ __forceinline__ float2 unf2(u64 v){ float2 p; asm("mov.b64 {%0,%1},%2;":"=f"(p.x),"=f"(p.y):"l"(v)); return p; }
__device__ __forceinline__ u64 f2fma(u64 a,u64 b,u64 c){ u64 d; asm("fma.rn.f32x2 %0,%1,%2,%3;":"=l"(d):"l"(a),"l"(b),"l"(c)); return d; }

// ---------------- conv1 (f32x2): (B,1,50,50) -> conv11x11 -> pool2 -> relu ----------
__global__ void conv1_kernel(const float* __restrict__ img,
                             const float* __restrict__ w,
                             const float* __restrict__ bias)
{
    __shared__ float sIm[2500];
    __shared__ __align__(8) u64 sW2[1210];   // {w,w} duplicated pairs
    __shared__ float sB[10];
    int b = blockIdx.x;
    int tid = threadIdx.x;  // 0..399
    for (int i = tid; i < 2500; i += 400) sIm[i] = img[b*2500 + i];
    for (int i = tid; i < 1210; i += 400) { float v = w[i]; sW2[i] = mkf2(v, v); }
    if (tid < 10) sB[tid] = bias[tid];
    __syncthreads();

    int oy = tid / 20, ox = tid % 20;
    u64 acc0[10], acc1[10];                  // {x,x+1} pairs for conv rows 2oy, 2oy+1
    u64 Z = mkf2(0.f, 0.f);
#pragma unroll
    for (int c = 0; c < 10; c++) { acc0[c] = Z; acc1[c] = Z; }
    int iy0 = 2*oy, ix0 = 2*ox;
    for (int ky = 0; ky < 11; ky++) {
        const float* r0 = &sIm[(iy0+ky)*50 + ix0];
        const float* r1 = r0 + 50;
        float f0[12], f1[12];
#pragma unroll
        for (int i = 0; i < 12; i++) { f0[i] = r0[i]; f1[i] = r1[i]; }
#pragma unroll
        for (int kx = 0; kx < 11; kx++) {
            u64 p0 = mkf2(f0[kx], f0[kx+1]);
            u64 p1 = mkf2(f1[kx], f1[kx+1]);
#pragma unroll
            for (int c = 0; c < 10; c++) {
                u64 wv = sW2[c*121 + ky*11 + kx];
                acc0[c] = f2fma(wv, p0, acc0[c]);
                acc1[c] = f2fma(wv, p1, acc1[c]);
            }
        }
    }
#pragma unroll
    for (int c = 0; c < 10; c++) {
        float2 a = unf2(acc0[c]);
        float2 d = unf2(acc1[c]);
        float m = fmaxf(fmaxf(a.x, a.y), fmaxf(d.x, d.y)) + sB[c];
        g_h1[((b*10 + c)*20 + oy)*20 + ox] = fmaxf(m, 0.0f);
    }
}

// ---------------- conv2 (f32x2): (B,10,20,20) -> conv5x5(20) -> pool4 -> relu --------
__global__ void conv2_kernel(const float* __restrict__ w,   // (20,10,5,5)
                             const float* __restrict__ bias)
{
    __shared__ __align__(8) float smA[5120];   // sIn (4000 used) then reused as sConv (5120)
    __shared__ __align__(8) u64 sW2[2500];     // [r=(ci*25+ky*5+kx)][j] channel-pair {w2j, w2j+1}
    int b = blockIdx.x;
    int tid = threadIdx.x;    // 0..319
    for (int i = tid; i < 4000; i += 320) smA[i] = g_h1[b*4000 + i];
    for (int i = tid; i < 2500; i += 320) {
        int r = i / 10, j = i % 10;
        sW2[i] = mkf2(w[(2*j)*250 + r], w[(2*j+1)*250 + r]);
    }
    __syncthreads();

    bool active = tid < 256;
    int ix = tid & 3, iy = (tid>>2)&3, px = (tid>>4)&3, py = (tid>>6)&3;
    int Y = py*4 + iy, X = px*4 + ix;
    u64 acc2[10];
    u64 Z = mkf2(0.f, 0.f);
#pragma unroll
    for (int j = 0; j < 10; j++) acc2[j] = Z;
    if (active) {
        for (int ci = 0; ci < 10; ci++) {
            const float* inp = &smA[ci*400 + Y*20 + X];
#pragma unroll
            for (int ky = 0; ky < 5; ky++) {
#pragma unroll
                for (int kx = 0; kx < 5; kx++) {
                    float pix = inp[ky*20 + kx];
                    u64 p2 = mkf2(pix, pix);
                    const u64* wp = &sW2[(ci*25 + ky*5 + kx)*10];
#pragma unroll
                    for (int j = 0; j < 10; j++)
                        acc2[j] = f2fma(wp[j], p2, acc2[j]);
                }
            }
        }
    }
    __syncthreads();
    float* sConv = smA;  // reuse: 20*16*16 = 5120 floats
    if (active) {
        int q = py*4 + px;
        int pos = iy*4 + ix;
#pragma unroll
        for (int j = 0; j < 10; j++) {
            float2 p = unf2(acc2[j]);
            sConv[((2*j)*16 + q)*16 + pos]   = p.x;
            sConv[((2*j+1)*16 + q)*16 + pos] = p.y;
        }
    }
    __syncthreads();
    {
        int c = tid / 16, qq = tid % 16;
        const float* p = &sConv[(c*16+qq)*16];
        float m = p[0];
#pragma unroll
        for (int k = 1; k < 16; k++) m = fmaxf(m, p[k]);
        m += bias[c];
        g_h2[b*320 + c*16 + qq] = fmaxf(m, 0.0f);
    }
}

// ---------------- weight transpose ----------------
__global__ void transpose_w(const float* __restrict__ w3, const float* __restrict__ w4,
                            const float* __restrict__ pw1, const float* __restrict__ vw1,
                            const float* __restrict__ pw2, const float* __restrict__ vw2,
                            const float* __restrict__ pw3, const float* __restrict__ vw3)
{
    int i = blockIdx.x*blockDim.x + threadIdx.x;
    if (i >= 118000) return;
    float v;
    if (i < 48000)       { int n=i%150, k=i/150;                 v = w3[n*320+k]; }
    else if (i < 63000)  { int j=i-48000;  int n=j%100, k=j/100; v = w4[n*150+k]; }
    else if (i < 77500)  { int j=i-63000;  int n=j%100, k=j/100; v = pw1[n*145+k]; }
    else if (i < 92000)  { int j=i-77500;  int n=j%100, k=j/100; v = vw1[n*145+k]; }
    else if (i < 102000) { int j=i-92000;  int n=j%100, k=j/100; v = pw2[n*100+k]; }
    else if (i < 112000) { int j=i-102000; int n=j%100, k=j/100; v = vw2[n*100+k]; }
    else if (i < 114000) { int j=i-112000; int n=j%20,  k=j/20;  v = pw3[n*100+k]; }
    else                 { int j=i-114000; int n=j%40,  k=j/40;  v = vw3[n*100+k]; }
    g_wT[i] = v;
}

// ---------------- fused MLP: 2 samples/block, deep-unroll ----------------------------
__global__ __launch_bounds__(256) void mlp_kernel(const float* __restrict__ xtraj,
    const float* __restrict__ b3, const float* __restrict__ b4,
    const float* __restrict__ pb1, const float* __restrict__ vb1,
    const float* __restrict__ pb2, const float* __restrict__ vb2,
    const float* __restrict__ pb3, const float* __restrict__ vb3)
{
    __shared__ float sA[2][324];
    __shared__ float sB[2][204];
    int b0 = blockIdx.x*2;
    int tid = threadIdx.x;

    for (int i = tid; i < 640; i += 256) {
        int s = i / 320, k = i % 320;
        sA[s][k] = g_h2[(b0+s)*320 + k];
    }
    __syncthreads();

    // L1: 320 -> 150 relu
    if (tid < 150) {
        const float* W = g_wT + tid;
        float a0=0.f, a1=0.f, c0=0.f, c1=0.f;
#pragma unroll 16
        for (int k = 0; k < 320; k += 2) {
            float w0 = W[k*150], w1 = W[(k+1)*150];
            a0 = fmaf(sA[0][k],   w0, a0);
            a1 = fmaf(sA[1][k],   w0, a1);
            c0 = fmaf(sA[0][k+1], w1, c0);
            c1 = fmaf(sA[1][k+1], w1, c1);
        }
        float bb = b3[tid];
        sB[0][tid] = fmaxf(a0+c0+bb, 0.f);
        sB[1][tid] = fmaxf(a1+c1+bb, 0.f);
    }
    __syncthreads();

    // L2: 150 -> 100 relu
    float l2a = 0.f, l2b = 0.f;
    if (tid < 100) {
        const float* W = g_wT + 48000 + tid;
        float bb = b4[tid];
        float a0=0.f, a1=0.f, c0=0.f, c1=0.f;
#pragma unroll 16
        for (int k = 0; k < 150; k += 2) {
            float w0 = W[k*100], w1 = W[(k+1)*100];
            a0 = fmaf(sB[0][k],   w0, a0);
            a1 = fmaf(sB[1][k],   w0, a1);
            c0 = fmaf(sB[0][k+1], w1, c0);
            c1 = fmaf(sB[1][k+1], w1, c1);
        }
        l2a = fmaxf(a0+c0+bb, 0.f);
        l2b = fmaxf(a1+c1+bb, 0.f);
    }
    __syncthreads();
    if (tid < 100) { sA[0][tid] = l2a; sA[1][tid] = l2b; }
    for (int i = tid; i < 90; i += 256) {
        int s = i / 45, j = i % 45;
        sA[s][100+j] = xtraj[(b0+s)*45 + j];
    }
    __syncthreads();

    // L3 dual: 145 -> 100 (p) / 100 (v), relu
    if (tid < 200) {
        int half = tid >= 100;
        int n = half ? tid - 100 : tid;
        const float* W = g_wT + (half ? 77500 : 63000) + n;
        float bb = (half ? vb1 : pb1)[n];
        float a0=0.f, a1=0.f, c0=0.f, c1=0.f;
#pragma unroll 16
        for (int k = 0; k < 144; k += 2) {
            float w0 = W[k*100], w1 = W[(k+1)*100];
            a0 = fmaf(sA[0][k],   w0, a0);
            a1 = fmaf(sA[1][k],   w0, a1);
            c0 = fmaf(sA[0][k+1], w1, c0);
            c1 = fmaf(sA[1][k+1], w1, c1);
        }
        {
            float w0 = W[144*100];
            a0 = fmaf(sA[0][144], w0, a0);
            a1 = fmaf(sA[1][144], w0, a1);
        }
        sB[0][tid] = fmaxf(a0+c0+bb, 0.f);
        sB[1][tid] = fmaxf(a1+c1+bb, 0.f);
    }
    __syncthreads();

    // L4 dual: 100 -> 100 each head, relu
    float l4a = 0.f, l4b = 0.f;
    if (tid < 200) {
        int half = tid >= 100;
        int n = half ? tid - 100 : tid;
        int xoff = half ? 100 : 0;
        const float* W = g_wT + (half ? 102000 : 92000) + n;
        float bb = (half ? vb2 : pb2)[n];
        float a0=0.f, a1=0.f, c0=0.f, c1=0.f;
#pragma unroll 16
        for (int k = 0; k < 100; k += 2) {
            float w0 = W[k*100], w1 = W[(k+1)*100];
            a0 = fmaf(sB[0][xoff+k],   w0, a0);
            a1 = fmaf(sB[1][xoff+k],   w0, a1);
            c0 = fmaf(sB[0][xoff+k+1], w1, c0);
            c1 = fmaf(sB[1][xoff+k+1], w1, c1);
        }
        l4a = fmaxf(a0+c0+bb, 0.f);
        l4b = fmaxf(a1+c1+bb, 0.f);
    }
    __syncthreads();
    if (tid < 200) { sA[0][tid] = l4a; sA[1][tid] = l4b; }
    __syncthreads();

    // L5 dual: 100 -> 20 (p_r), 100 -> 40 (v), linear, to global
    if (tid < 20) {
        const float* W = g_wT + 112000 + tid;
        float bb = pb3[tid];
        float a0=0.f, a1=0.f, c0=0.f, c1=0.f;
#pragma unroll 16
        for (int k = 0; k < 100; k += 2) {
            float w0 = W[k*20], w1 = W[(k+1)*20];
            a0 = fmaf(sA[0][k],   w0, a0);
            a1 = fmaf(sA[1][k],   w0, a1);
            c0 = fmaf(sA[0][k+1], w1, c0);
            c1 = fmaf(sA[1][k+1], w1, c1);
        }
        g_pr[(b0+0)*20 + tid] = a0+c0+bb;
        g_pr[(b0+1)*20 + tid] = a1+c1+bb;
    } else if (tid >= 32 && tid < 72) {
        int n = tid - 32;
        const float* W = g_wT + 114000 + n;
        float bb = vb3[n];
        float a0=0.f, a1=0.f, c0=0.f, c1=0.f;
#pragma unroll 16
        for (int k = 0; k < 100; k += 2) {
            float w0 = W[k*40], w1 = W[(k+1)*40];
            a0 = fmaf(sA[0][100+k],   w0, a0);
            a1 = fmaf(sA[1][100+k],   w0, a1);
            c0 = fmaf(sA[0][100+k+1], w1, c0);
            c1 = fmaf(sA[1][100+k+1], w1, c1);
        }
        g_v[(b0+0)*40 + n] = a0+c0+bb;
        g_v[(b0+1)*40 + n] = a1+c1+bb;
    }
}

// ---------------- PDHG solver (scalar, proven; issue-bound) + fused tail --------------
struct Co {
    float a24,a25,a26,a27,a28,a29,a2a,a2b;
    float v0,v1,v2,v3,v4,v5;
    float fc0,fc1,fc2,fc3,fc4,fc5;
    float fe0,fe1,fe2,fe3,fe4,fe5,fe6,fe7;
};

__device__ __forceinline__ void amul(const Co& c, const float* s, float* az)
{
    az[0]  = s[4]+s[5]+s[6]+s[7]+s[8]+s[9];
    az[1]  = s[10]+s[11];
    {
        float p = c.a26*s[6] + c.a24*s[4] + c.a27*s[7] + c.a25*s[5];
        float q = c.a2a*s[10] + c.a28*s[8] + c.a2b*s[11] + c.a29*s[9];
        az[2] = p + q;
    }
    az[3]  = s[0] - c.v0*s[12] - c.v2*s[14];
    az[4]  = s[2] - c.v1*s[12] - c.v3*s[14];
    az[5]  = s[12] + s[14];
    az[6]  = s[1] - c.v2*s[13] - c.v4*s[15];
    az[7]  = s[3] - c.v3*s[13] - c.v5*s[15];
    az[8]  = s[13] + s[15];
    az[9]  = c.fc0*s[16] + c.fc2*s[18] - s[4];
    az[10] = c.fc1*s[16] + c.fc3*s[18] - s[6];
    az[11] = c.fc2*s[17] + c.fc4*s[19] - s[5];
    az[12] = c.fc3*s[17] + c.fc5*s[19] - s[7];
    az[13] = c.fe0*s[20] + c.fe2*s[21] - s[8];
    az[14] = c.fe1*s[20] + c.fe3*s[21] - s[10];
    az[15] = c.fe4*s[22] + c.fe6*s[23] - s[9];
    az[16] = c.fe5*s[22] + c.fe7*s[23] - s[11];
}

__device__ __forceinline__ void atmul(const Co& c, const float* y, float* g)
{
    g[0]  = y[3];  g[1] = y[6];  g[2] = y[4];  g[3] = y[7];
    g[4]  = y[0] + c.a24*y[2] - y[9];
    g[5]  = y[0] + c.a25*y[2] - y[11];
    g[6]  = y[0] + c.a26*y[2] - y[10];
    g[7]  = y[0] + c.a27*y[2] - y[12];
    g[8]  = y[0] + c.a28*y[2] - y[13];
    g[9]  = y[0] + c.a29*y[2] - y[15];
    g[10] = y[1] + c.a2a*y[2] - y[14];
    g[11] = y[1] + c.a2b*y[2] - y[16];
    g[12] = -c.v0*y[3] - c.v1*y[4] + y[5];
    g[13] = -c.v2*y[6] - c.v3*y[7] + y[8];
    g[14] = -c.v2*y[3] - c.v3*y[4] + y[5];
    g[15] = -c.v4*y[6] - c.v5*y[7] + y[8];
    g[16] = c.fc0*y[9]  + c.fc1*y[10];
    g[17] = c.fc2*y[11] + c.fc3*y[12];
    g[18] = c.fc2*y[9]  + c.fc3*y[10];
    g[19] = c.fc4*y[11] + c.fc5*y[12];
    g[20] = c.fe0*y[13] + c.fe1*y[14];
    g[21] = c.fe2*y[13] + c.fe3*y[14];
    g[22] = c.fe4*y[15] + c.fe5*y[16];
    g[23] = c.fe6*y[15] + c.fe7*y[16];
}

__global__ __launch_bounds__(32) void pdhg_kernel(const float* __restrict__ xtraj,
                                                  const float* __restrict__ x,
                                                  float* __restrict__ out)
{
    int p = blockIdx.x*blockDim.x + threadIdx.x;
    if (p >= NPROB) return;
    int b = p / TT, t = p % TT;
    const float* xt = xtraj + b*45;
    const float* xx = x + b*160;

    float r0 = xt[t], r1 = xt[5+t];
    float ddr0 = xt[30+t], ddr1 = xt[35+t], ddr2 = xt[40+t];

    Co c;
    c.fc0 = xx[20+t]; c.fc1 = xx[25+t]; c.fc2 = xx[30+t];
    c.fc3 = xx[35+t]; c.fc4 = xx[40+t]; c.fc5 = xx[45+t];
    float pe0 = xx[60+t], pe1 = xx[65+t], pe2 = xx[70+t], pe3 = xx[75+t];
    c.fe0 = xx[80+t];  c.fe1 = xx[85+t];  c.fe2 = xx[90+t];  c.fe3 = xx[95+t];
    c.fe4 = xx[100+t]; c.fe5 = xx[105+t]; c.fe6 = xx[110+t]; c.fe7 = xx[115+t];
    const float* vv = g_v + b*40;
    c.v0 = vv[t];    c.v1 = vv[5+t];  c.v2 = vv[10+t];
    c.v3 = vv[15+t]; c.v4 = vv[20+t]; c.v5 = vv[25+t];
    const float* pp = g_pr + b*20;
    float pr0 = pp[t], pr1 = pp[5+t], pr2 = pp[10+t], pr3 = pp[15+t];
    c.a24 = -(pr2 - r1); c.a25 = -(pr3 - r1); c.a26 = pr0 - r0; c.a27 = pr1 - r0;
    c.a28 = -(pe2 - r1); c.a29 = -(pe3 - r1); c.a2a = pe0 - r0; c.a2b = pe1 - r0;

    // ----- spectral norm: 25 power iterations -----
    float u[24];
#pragma unroll
    for (int i = 0; i < 24; i++) u[i] = 1.0f;
    for (int it = 0; it < 25; it++) {
        float w[17], un[24];
        amul(c, u, w);
        atmul(c, w, un);
        float s = 0.0f;
#pragma unroll
        for (int i = 0; i < 24; i++) s += un[i]*un[i];
        float inv = 1.0f/(sqrtf(s) + 1e-12f);
#pragma unroll
        for (int i = 0; i < 24; i++) u[i] = un[i]*inv;
    }
    float w17[17];
    amul(c, u, w17);
    float s = 0.0f;
#pragma unroll
    for (int e = 0; e < 17; e++) s += w17[e]*w17[e];
    float L = sqrtf(s);
    float tau = 0.9f/(L + 1e-8f);
    float sig = tau;

    // ----- PDHG, 400 iterations -----
    float z[24], zb[24], y[17];
#pragma unroll
    for (int i = 0; i < 24; i++) { z[i] = 0.0f; zb[i] = 0.0f; }
#pragma unroll
    for (int e = 0; e < 17; e++) y[e] = 0.0f;

    for (int it = 0; it < 400; it++) {
        float az[17];
        amul(c, zb, az);
        y[0] += sig*(az[0] - ddr0);
        y[1] += sig*(az[1] - ddr1);
        y[2] += sig*(az[2] - ddr2);
        y[3] += sig*az[3];
        y[4] += sig*az[4];
        y[5] += sig*(az[5] - 1.0f);
        y[6] += sig*az[6];
        y[7] += sig*az[7];
        y[8] += sig*(az[8] - 1.0f);
#pragma unroll
        for (int e = 9; e < 17; e++) y[e] += sig*az[e];

        float g[24];
        atmul(c, y, g);
#pragma unroll
        for (int i = 0; i < 24; i++) g[i] = z[i] - tau*g[i];

        float zn[24];
#pragma unroll
        for (int i = 0; i < 4; i++) zn[i] = g[i];
#pragma unroll
        for (int i = 4; i < 8; i++) {
            float a = fabsf(g[i]) - tau;
            zn[i] = (a > 0.0f) ? copysignf(a, g[i]) : 0.0f;
        }
#pragma unroll
        for (int i = 8; i < 12; i++) zn[i] = g[i];
#pragma unroll
        for (int i = 12; i < 24; i++) zn[i] = fmaxf(g[i], 0.0f);
#pragma unroll
        for (int i = 0; i < 24; i++) {
            zb[i] = 2.0f*zn[i] - z[i];
            z[i] = zn[i];
        }
    }

    // ----- write p, f parts (scaled by 100) -----
#pragma unroll
    for (int i = 0; i < 4; i++) out[b*100 + i*5 + t]      = 100.0f * z[i];
#pragma unroll
    for (int i = 0; i < 4; i++) out[b*100 + 20 + i*5 + t] = 100.0f * z[4+i];

    // ----- fused tail: this thread writes 12 of the 60 tail outputs of sample b -----
#pragma unroll
    for (int j = 0; j < 12; j++) {
        int jj = t*12 + j;
        if (jj < 20) out[b*100 + 40 + jj] = 1000.0f*(g_pr[b*20 + jj] - xx[jj]);
        else {
            int k = jj - 20;
            out[b*100 + 60 + k] = 1000.0f*(g_v[b*40 + k] - xx[120 + k]);
        }
    }
}

// ---------------- launch ----------------
extern "C" void kernel_launch(void* const* d_in, const int* in_sizes, int n_in,
                              void* d_out, int out_size)
{
    const float* xtraj = (const float*)d_in[0];
    const float* x     = (const float*)d_in[1];
    const float* x_img = (const float*)d_in[2];
    const float* cw1   = (const float*)d_in[3];
    const float* cb1   = (const float*)d_in[4];
    const float* cw2   = (const float*)d_in[5];
    const float* cb2   = (const float*)d_in[6];
    const float* w3    = (const float*)d_in[7];
    const float* b3    = (const float*)d_in[8];
    const float* w4    = (const float*)d_in[9];
    const float* b4    = (const float*)d_in[10];
    const float* pw1   = (const float*)d_in[11];
    const float* pb1   = (const float*)d_in[12];
    const float* pw2   = (const float*)d_in[13];
    const float* pb2   = (const float*)d_in[14];
    const float* pw3   = (const float*)d_in[15];
    const float* pb3   = (const float*)d_in[16];
    const float* vw1   = (const float*)d_in[17];
    const float* vb1   = (const float*)d_in[18];
    const float* vw2   = (const float*)d_in[19];
    const float* vb2   = (const float*)d_in[20];
    const float* vw3   = (const float*)d_in[21];
    const float* vb3   = (const float*)d_in[22];
    float* out = (float*)d_out;

    transpose_w<<<(118000 + 255)/256, 256>>>(w3, w4, pw1, vw1, pw2, vw2, pw3, vw3);
    conv1_kernel<<<BATCH, 400>>>(x_img, cw1, cb1);
    conv2_kernel<<<BATCH, 320>>>(cw2, cb2);
    mlp_kernel<<<BATCH/2, 256>>>(xtraj, b3, b4, pb1, vb1, pb2, vb2, pb3, vb3);
    pdhg_kernel<<<(NPROB + 31)/32, 32>>>(xtraj, x, out);
}